// round 17
// baseline (speedup 1.0000x reference)
#include <cuda_runtime.h>
#include <cuda_fp16.h>
#include <cstdint>

#define BT 64
#define CH 64
#define LL 1024
#define BM 128
#define BN 64
#define NT (LL/BN)

// Scratch, all [b][c][l], single fp16 each.
__device__ __half g_q[(size_t)BT*CH*LL];
__device__ __half g_k[(size_t)BT*CH*LL];
__device__ __half g_v[(size_t)BT*CH*LL];

// ---------------- helpers ----------------
__device__ __forceinline__ uint32_t cvta_smem(const void* p) {
    uint32_t a;
    asm("{ .reg .u64 t; cvta.to.shared.u64 t, %1; cvt.u32.u64 %0, t; }" : "=r"(a) : "l"(p));
    return a;
}
#define CP16(dst, src) \
    asm volatile("cp.async.cg.shared.global [%0], [%1], 16;" :: "r"(dst), "l"(src) : "memory")
#define CP_COMMIT() asm volatile("cp.async.commit_group;" ::: "memory")
#define CP_WAIT(n)  asm volatile("cp.async.wait_group %0;" :: "n"(n) : "memory")

#define LDSM4(r0, r1, r2, r3, addr) \
    asm volatile("ldmatrix.sync.aligned.m8n8.x4.shared.b16 {%0,%1,%2,%3}, [%4];" \
        : "=r"(r0), "=r"(r1), "=r"(r2), "=r"(r3) : "r"(addr))
#define LDSM4T(r0, r1, r2, r3, addr) \
    asm volatile("ldmatrix.sync.aligned.m8n8.x4.trans.shared.b16 {%0,%1,%2,%3}, [%4];" \
        : "=r"(r0), "=r"(r1), "=r"(r2), "=r"(r3) : "r"(addr))

#define MMA_FP(d, a, b0, b1) \
    asm volatile("mma.sync.aligned.m16n8k16.row.col.f32.f16.f16.f32 " \
        "{%0,%1,%2,%3}, {%4,%5,%6,%7}, {%8,%9}, {%0,%1,%2,%3};" \
        : "+f"((d)[0]), "+f"((d)[1]), "+f"((d)[2]), "+f"((d)[3]) \
        : "r"((a)[0]), "r"((a)[1]), "r"((a)[2]), "r"((a)[3]), "r"(b0), "r"(b1))

__device__ __forceinline__ uint32_t cvt_f16x2(float hi, float lo) {
    uint32_t d; asm("cvt.rn.f16x2.f32 %0, %1, %2;" : "=r"(d) : "f"(hi), "f"(lo)); return d;
}
__device__ __forceinline__ uint32_t ex2_f16x2(uint32_t a) {
    uint32_t d; asm("ex2.approx.f16x2 %0, %1;" : "=r"(d) : "r"(a)); return d;
}
__device__ __forceinline__ float2 ffma2(float2 a, float2 b, float2 c) {
    unsigned long long A = *reinterpret_cast<unsigned long long*>(&a);
    unsigned long long B = *reinterpret_cast<unsigned long long*>(&b);
    unsigned long long Cc = *reinterpret_cast<unsigned long long*>(&c);
    unsigned long long D;
    asm("fma.rn.f32x2 %0, %1, %2, %3;" : "=l"(D) : "l"(A), "l"(B), "l"(Cc));
    return *reinterpret_cast<float2*>(&D);
}
__device__ __forceinline__ uint32_t lo_f16x2(float a, float b, uint32_t hi) {
    __half2 h = *reinterpret_cast<__half2*>(&hi);
    float2 hf = __half22float2(h);
    return cvt_f16x2(b - hf.y, a - hf.x);
}

#define ONES16X2 0x3C003C00u
#define LOG2E    1.4426950408889634f
// SW128 swizzle for 128B rows and 256B rows.
#define SWZ(o)    ((o) ^ (((o) >> 3) & 0x70))
#define SWZ256(o) ((o) ^ (((o) >> 4) & 0x70))

// ---------------------------------------------------------------------------
// Kernel 1 (v7, unchanged from R16 pass): QKV projection on tensor cores.
// ---------------------------------------------------------------------------
#define XH_OFF 0u
#define WH_OFF 17408u
#define WL_OFF 45056u
#define QKV_SMEM 73728

__global__ __launch_bounds__(256, 3) void qkv_kernel(
    const float* __restrict__ x,
    const float* __restrict__ Wq, const float* __restrict__ bq,
    const float* __restrict__ Wk, const float* __restrict__ bk,
    const float* __restrict__ Wv, const float* __restrict__ bv)
{
    extern __shared__ char sm[];
    const uint32_t smb = cvta_smem(sm);
    const int b    = blockIdx.y;
    const int l0   = blockIdx.x * 128;
    const int tid  = threadIdx.x;
    const int w    = tid >> 5;
    const int lane = tid & 31;
    const int g    = lane >> 2;
    const int tc   = lane & 3;

    #pragma unroll
    for (int i = 0; i < 12; i++) {
        const int ci = tid + i * 256;
        const int r  = ci >> 4;
        const int c4 = ci & 15;
        const float* ws = (r < 64) ? Wq : ((r < 128) ? Wk : Wv);
        float4 wv = *reinterpret_cast<const float4*>(ws + (r & 63) * 64 + c4 * 4);
        uint32_t h0 = cvt_f16x2(wv.y, wv.x);
        uint32_t h1 = cvt_f16x2(wv.w, wv.z);
        uint32_t l0r = lo_f16x2(wv.x, wv.y, h0);
        uint32_t l1r = lo_f16x2(wv.z, wv.w, h1);
        const uint32_t off = (uint32_t)r * 144 + (uint32_t)c4 * 8;
        *reinterpret_cast<uint2*>(sm + WH_OFF + off) = make_uint2(h0, h1);
        *reinterpret_cast<uint2*>(sm + WL_OFF + off) = make_uint2(l0r, l1r);
    }

    #pragma unroll
    for (int i = 0; i < 8; i++) {
        const int ci = tid + i * 256;
        const int c  = ci >> 5;
        const int lq = ci & 31;
        float4 xv = *reinterpret_cast<const float4*>(
            x + ((size_t)b * CH + c) * LL + l0 + lq * 4);
        uint32_t h0 = cvt_f16x2(xv.y, xv.x);
        uint32_t h1 = cvt_f16x2(xv.w, xv.z);
        const uint32_t off = (uint32_t)c * 272 + (uint32_t)lq * 8;
        *reinterpret_cast<uint2*>(sm + XH_OFF + off) = make_uint2(h0, h1);
    }
    __syncthreads();

    uint32_t bh[2][8];
    #pragma unroll
    for (int nb = 0; nb < 2; nb++) {
        #pragma unroll
        for (int h = 0; h < 2; h++) {
            uint32_t a = smb + XH_OFF + (uint32_t)(h * 32 + lane) * 272
                       + (uint32_t)(w * 16 + nb * 8) * 2;
            LDSM4T(bh[nb][h*4+0], bh[nb][h*4+1], bh[nb][h*4+2], bh[nb][h*4+3], a);
        }
    }

    const uint32_t arow = (uint32_t)(((lane >> 3) & 1) * 8 + (lane & 7));
    const uint32_t acol = (uint32_t)(((lane >> 4) & 1) * 16);

    #pragma unroll
    for (int m = 0; m < 3; m++) {
        float acc[4][2][4];
        #pragma unroll
        for (int mb = 0; mb < 4; mb++)
            #pragma unroll
            for (int nb = 0; nb < 2; nb++)
                #pragma unroll
                for (int r = 0; r < 4; r++) acc[mb][nb][r] = 0.f;

        #pragma unroll
        for (int mb = 0; mb < 4; mb++) {
            #pragma unroll
            for (int ks = 0; ks < 4; ks++) {
                uint32_t ah[4], al[4];
                uint32_t a = smb + WH_OFF
                           + ((uint32_t)(m * 64 + mb * 16) + arow) * 144
                           + (uint32_t)ks * 32 + acol;
                LDSM4(ah[0], ah[1], ah[2], ah[3], a);
                if (m < 2) LDSM4(al[0], al[1], al[2], al[3], a + (WL_OFF - WH_OFF));
                #pragma unroll
                for (int nb = 0; nb < 2; nb++) {
                    MMA_FP(acc[mb][nb], ah, bh[nb][2*ks], bh[nb][2*ks+1]);
                    if (m < 2)
                        MMA_FP(acc[mb][nb], al, bh[nb][2*ks], bh[nb][2*ks+1]);
                }
            }
        }

        const float* bias = (m == 0) ? bq : (m == 1 ? bk : bv);
        __half* dst = (m == 0) ? g_q : (m == 1 ? g_k : g_v);
        #pragma unroll
        for (int mb = 0; mb < 4; mb++) {
            const float bl0 = __ldg(bias + mb * 16 + g);
            const float bl1 = __ldg(bias + mb * 16 + 8 + g);
            #pragma unroll
            for (int nb = 0; nb < 2; nb++) {
                const int l = l0 + w * 16 + nb * 8 + tc * 2;
                uint32_t v0 = cvt_f16x2(acc[mb][nb][1] + bl0, acc[mb][nb][0] + bl0);
                uint32_t v1 = cvt_f16x2(acc[mb][nb][3] + bl1, acc[mb][nb][2] + bl1);
                *reinterpret_cast<uint32_t*>(
                    dst + ((size_t)b * CH + mb * 16 + g) * LL + l) = v0;
                *reinterpret_cast<uint32_t*>(
                    dst + ((size_t)b * CH + mb * 16 + 8 + g) * LL + l) = v1;
            }
        }
    }
}

// ---------------------------------------------------------------------------
// Kernel 2 (v5): HMMA flash attention, m32 per warp (BM=128, 4 warps).
// Each K/V fragment load now feeds 2x the MMAs -> smem read traffic halves.
// Q 256B swizzled rows; KV 128B swizzled rows; 3 buffers, 1 barrier/tile.
// ---------------------------------------------------------------------------
#define B0_OFF 16384u
#define TBUF   16384u
#define VOFF   8192u
#define SM_TOT (B0_OFF + 3u*TBUF)   // 65536

__device__ __forceinline__ void load_kv(uint32_t buf, int b, int j0, int tid) {
    #pragma unroll
    for (int t = tid; t < 512; t += 128) {
        int row = t >> 3, ch = t & 7;
        uint32_t o = SWZ((uint32_t)row * 128 + (uint32_t)ch * 16);
        const size_t e = ((size_t)b * CH + row) * LL + j0;
        CP16(buf + o,        (const char*)(g_k + e) + ch * 16);
        CP16(buf + VOFF + o, (const char*)(g_v + e) + ch * 16);
    }
}

__global__ __launch_bounds__(128, 2) void attn_kernel(float* __restrict__ out)
{
    extern __shared__ char sm[];
    const uint32_t smb = cvta_smem(sm);
    const int b    = blockIdx.y;
    const int i0   = blockIdx.x * BM;
    const int tid  = threadIdx.x;
    const int w    = tid >> 5;      // warp owns i-rows [w*32, w*32+32)
    const int lane = tid & 31;
    const int g    = lane >> 2;
    const int tc   = lane & 3;

    // Q tile [64 c][128 i], swizzled 256B rows at offset 0.
    #pragma unroll
    for (int t = tid; t < 1024; t += 128) {
        int row = t >> 4, ch = t & 15;
        uint32_t o = SWZ256((uint32_t)row * 256 + (uint32_t)ch * 16);
        const size_t e = ((size_t)b * CH + row) * LL + i0;
        CP16(smb + o, (const char*)(g_q + e) + ch * 16);
    }
    CP_COMMIT();
    load_kv(smb + B0_OFF, b, 0, tid);           CP_COMMIT();
    load_kv(smb + B0_OFF + TBUF, b, BN, tid);   CP_COMMIT();

    CP_WAIT(2);
    __syncthreads();

    // Q A-fragments (m32: two m16 row-blocks per warp) via ldmatrix.trans
    uint32_t qf[4][2][4];
    {
        const int lr   = lane & 7;
        const int csel = (lane >> 4) & 1;
        const int isel = (lane >> 3) & 1;
        #pragma unroll
        for (int ks = 0; ks < 4; ks++) {
            #pragma unroll
            for (int rb = 0; rb < 2; rb++) {
                uint32_t row = (uint32_t)(ks * 16 + lr + csel * 8);
                uint32_t bc  = (uint32_t)(w * 32 + rb * 16 + isel * 8) * 2;
                LDSM4T(qf[ks][rb][0], qf[ks][rb][1], qf[ks][rb][2], qf[ks][rb][3],
                       smb + SWZ256(row * 256 + bc));
            }
        }
    }

    float oa[2][8][4];
    #pragma unroll
    for (int rb = 0; rb < 2; rb++)
        #pragma unroll
        for (int c = 0; c < 8; c++)
            #pragma unroll
            for (int r = 0; r < 4; r++) oa[rb][c][r] = 0.f;
    float rsacc[2][4] = {{0.f,0.f,0.f,0.f},{0.f,0.f,0.f,0.f}};
    float m[4] = {-1e30f, -1e30f, -1e30f, -1e30f};

    #pragma unroll 1
    for (int jt = 0; jt < NT; jt++) {
        if (jt < NT - 1) CP_WAIT(1); else CP_WAIT(0);
        __syncthreads();

        if (jt < NT - 2) {
            load_kv(smb + B0_OFF + (uint32_t)((jt + 2) % 3) * TBUF, b, (jt + 2) * BN, tid);
            CP_COMMIT();
        }

        const uint32_t kb = smb + B0_OFF + (uint32_t)(jt % 3) * TBUF;

        // ---- S = q * k (m32: 8 MMA per jb) ----
        float s[8][2][4];
        #pragma unroll
        for (int jb = 0; jb < 8; jb++)
            #pragma unroll
            for (int rb = 0; rb < 2; rb++)
                #pragma unroll
                for (int r = 0; r < 4; r++) s[jb][rb][r] = 0.f;

        #pragma unroll
        for (int jb = 0; jb < 8; jb++) {
            uint32_t khr[8];
            #pragma unroll
            for (int h = 0; h < 2; h++) {
                uint32_t row = (uint32_t)(h * 32 + lane);
                uint32_t a = kb + SWZ(row * 128 + (uint32_t)jb * 16);
                LDSM4T(khr[h*4+0], khr[h*4+1], khr[h*4+2], khr[h*4+3], a);
            }
            #pragma unroll
            for (int ks = 0; ks < 4; ks++) {
                MMA_FP(s[jb][0], qf[ks][0], khr[2*ks], khr[2*ks+1]);
                MMA_FP(s[jb][1], qf[ks][1], khr[2*ks], khr[2*ks+1]);
            }
        }

        // ---- online softmax (4 row streams per thread) ----
        float mt[4];
        mt[0] = fmaxf(s[0][0][0], s[0][0][1]);
        mt[1] = fmaxf(s[0][0][2], s[0][0][3]);
        mt[2] = fmaxf(s[0][1][0], s[0][1][1]);
        mt[3] = fmaxf(s[0][1][2], s[0][1][3]);
        #pragma unroll
        for (int jb = 1; jb < 8; jb++) {
            mt[0] = fmaxf(mt[0], fmaxf(s[jb][0][0], s[jb][0][1]));
            mt[1] = fmaxf(mt[1], fmaxf(s[jb][0][2], s[jb][0][3]));
            mt[2] = fmaxf(mt[2], fmaxf(s[jb][1][0], s[jb][1][1]));
            mt[3] = fmaxf(mt[3], fmaxf(s[jb][1][2], s[jb][1][3]));
        }
        #pragma unroll
        for (int e = 0; e < 4; e++) {
            mt[e] = fmaxf(mt[e], __shfl_xor_sync(0xffffffffu, mt[e], 1));
            mt[e] = fmaxf(mt[e], __shfl_xor_sync(0xffffffffu, mt[e], 2));
        }

        float M[4];
        bool nochange = true;
        #pragma unroll
        for (int e = 0; e < 4; e++) {
            M[e] = fmaxf(m[e], mt[e]);
            nochange = nochange && (M[e] == m[e]);
        }
        if (!__all_sync(0xffffffffu, nochange)) {
            float c[4];
            #pragma unroll
            for (int e = 0; e < 4; e++) c[e] = __expf(m[e] - M[e]);
            #pragma unroll
            for (int rb = 0; rb < 2; rb++) {
                rsacc[rb][0] *= c[rb*2];
                rsacc[rb][2] *= c[rb*2+1];
                #pragma unroll
                for (int cb = 0; cb < 8; cb++) {
                    oa[rb][cb][0] *= c[rb*2];   oa[rb][cb][1] *= c[rb*2];
                    oa[rb][cb][2] *= c[rb*2+1]; oa[rb][cb][3] *= c[rb*2+1];
                }
            }
        }
        #pragma unroll
        for (int e = 0; e < 4; e++) m[e] = M[e];

        // ---- P = 2^((s-M)*log2e) ----
        const float2 l2e = make_float2(LOG2E, LOG2E);
        float2 mb[4];
        #pragma unroll
        for (int e = 0; e < 4; e++) mb[e] = make_float2(-M[e]*LOG2E, -M[e]*LOG2E);
        uint32_t pf[2][4][4];
        #pragma unroll
        for (int jb = 0; jb < 8; jb++) {
            const int ks = jb >> 1, pos = (jb & 1) * 2;
            #pragma unroll
            for (int rb = 0; rb < 2; rb++) {
                float2 t01 = ffma2(make_float2(s[jb][rb][0], s[jb][rb][1]), l2e, mb[rb*2]);
                float2 t23 = ffma2(make_float2(s[jb][rb][2], s[jb][rb][3]), l2e, mb[rb*2+1]);
                pf[rb][ks][pos    ] = ex2_f16x2(cvt_f16x2(t01.y, t01.x));
                pf[rb][ks][pos + 1] = ex2_f16x2(cvt_f16x2(t23.y, t23.x));
            }
        }

        // ---- row sums via ones-MMA ----
        #pragma unroll
        for (int ks = 0; ks < 4; ks++) {
            MMA_FP(rsacc[0], pf[0][ks], ONES16X2, ONES16X2);
            MMA_FP(rsacc[1], pf[1][ks], ONES16X2, ONES16X2);
        }

        // ---- O += P V ----
        #pragma unroll
        for (int cb = 0; cb < 8; cb++) {
            #pragma unroll
            for (int kp = 0; kp < 2; kp++) {
                uint32_t row = (uint32_t)(cb * 8 + (lane & 7));
                uint32_t bc  = (uint32_t)((lane >> 3) * 16 + kp * 64);
                uint32_t vv[4];
                LDSM4(vv[0], vv[1], vv[2], vv[3], kb + VOFF + SWZ(row * 128 + bc));
                #pragma unroll
                for (int k2 = 0; k2 < 2; k2++) {
                    MMA_FP(oa[0][cb], pf[0][kp*2 + k2], vv[k2*2], vv[k2*2+1]);
                    MMA_FP(oa[1][cb], pf[1][kp*2 + k2], vv[k2*2], vv[k2*2+1]);
                }
            }
        }
    }

    // ---- epilogue ----
    #pragma unroll
    for (int rb = 0; rb < 2; rb++) {
        const float inv0 = 1.f / rsacc[rb][0];
        const float inv1 = 1.f / rsacc[rb][2];
        const int r0 = i0 + w * 32 + rb * 16 + g;
        const int r1 = r0 + 8;
        #pragma unroll
        for (int cb = 0; cb < 8; cb++) {
            const int c = cb * 8 + tc * 2;
            float* p0 = out + ((size_t)b * CH + c) * LL;
            p0[r0]      = oa[rb][cb][0] * inv0;
            p0[LL + r0] = oa[rb][cb][1] * inv0;
            p0[r1]      = oa[rb][cb][2] * inv1;
            p0[LL + r1] = oa[rb][cb][3] * inv1;
        }
    }
}

// ---------------------------------------------------------------------------
extern "C" void kernel_launch(void* const* d_in, const int* in_sizes, int n_in,
                              void* d_out, int out_size)
{
    (void)in_sizes; (void)n_in; (void)out_size;
    const float* x  = (const float*)d_in[0];
    const float* Wq = (const float*)d_in[1];
    const float* bq = (const float*)d_in[2];
    const float* Wk = (const float*)d_in[3];
    const float* bk = (const float*)d_in[4];
    const float* Wv = (const float*)d_in[5];
    const float* bv = (const float*)d_in[6];
    float* out = (float*)d_out;

    cudaFuncSetAttribute(qkv_kernel, cudaFuncAttributeMaxDynamicSharedMemorySize, QKV_SMEM);
    qkv_kernel<<<dim3(LL / 128, BT), 256, QKV_SMEM>>>(x, Wq, bq, Wk, bk, Wv, bv);

    cudaFuncSetAttribute(attn_kernel, cudaFuncAttributeMaxDynamicSharedMemorySize, SM_TOT);
    attn_kernel<<<dim3(LL / BM, BT), 128, SM_TOT>>>(out);
}